// round 1
// baseline (speedup 1.0000x reference)
#include <cuda_runtime.h>
#include <math.h>

// Problem dims (fixed)
#define BT_  8
#define L_   8192
#define H_   512
#define P_   256
#define M_TOT 65536            // BT_*L_
#define NC   64                // chunks per sequence
#define LCH  128               // L_/NC
#define LOG_LCH 7

// Scratch (device globals — allocation-free per harness rules)
__device__ float g_Bu[(size_t)M_TOT * 512];   // [m][2p + (0=R,1=I)]
__device__ float g_ys[(size_t)M_TOT * 512];   // [m][2p + (0=R,1=I)]
__device__ float g_Wg[512 * 512];             // GEMM1 weight [n=2p+c][h]
__device__ float g_W2[512 * 512];             // GEMM2 weight [n=h][k=2p+c]
__device__ float4 g_T[BT_ * NC * 256];        // chunk-local final states
__device__ float4 g_S[BT_ * NC * 256];        // chunk prefix states

// ---------------------------------------------------------------------------
// Weight prep: pack complex B into [2p|2p+1][h] rows, C into [h][2p|2p+1] rows
// ---------------------------------------------------------------------------
__global__ void prep_weights(const float* __restrict__ B, const float* __restrict__ C)
{
    int i = blockIdx.x * blockDim.x + threadIdx.x;  // 0 .. 131071
    int p = i >> 9;
    int h = i & 511;
    g_Wg[(2 * p) * 512 + h]     = B[((p << 9) + h) * 2 + 0];
    g_Wg[(2 * p + 1) * 512 + h] = B[((p << 9) + h) * 2 + 1];
    g_W2[(h << 9) + 2 * p]      = C[((h << 8) + p) * 2 + 0];
    g_W2[(h << 9) + 2 * p + 1]  = -C[((h << 8) + p) * 2 + 1];
}

// ---------------------------------------------------------------------------
// Per-p transition parameters, matching reference fp32 rounding exactly.
// sigmoid in double -> round to fp32 (reference is XLA fp32 logistic, <=~2ulp
// from true; minimizing our own error minimizes L-amplified phase drift).
// ---------------------------------------------------------------------------
__device__ __forceinline__ void get_params(const float* __restrict__ sp,
                                           const float* __restrict__ ap, int p,
                                           float& s, float& s2,
                                           float& mB, float& mC, float& mD)
{
    double sd = 1.0 / (1.0 + exp(-(double)sp[p]));
    s = (float)sd;
    float a = fmaxf(ap[p], 0.0f);
    mB = -__fmul_rn(s, a);                       // -steps*A
    mC = s;                                      // steps
    s2 = __fmul_rn(s, s);                        // steps**2
    mD = __fsub_rn(1.0f, __fmul_rn(s2, a));      // 1 - steps**2 * A
}

// ---------------------------------------------------------------------------
// Pass 1: per-chunk local scan from zero; record final (z1,z2) for R and I.
// Thread = p, block = (b, chunk). Bu rows are [m][2p..] -> float2 coalesced.
// ---------------------------------------------------------------------------
__global__ void scan_partial(const float* __restrict__ sp, const float* __restrict__ ap)
{
    int p = threadIdx.x;
    int bc = blockIdx.x;
    int b = bc / NC, c = bc % NC;
    float s, s2, mB, mC, mD;
    get_params(sp, ap, p, s, s2, mB, mC, mD);

    float z1R = 0.f, z2R = 0.f, z1I = 0.f, z2I = 0.f;
    const float2* Bp = (const float2*)(g_Bu + (size_t)(b * L_ + c * LCH) * 512) + p;

#pragma unroll 4
    for (int j = 0; j < LCH; j++) {
        float2 bu = Bp[(size_t)j * 256];
        float F1R = s * bu.x,  F1I = s * bu.y;
        float F2R = s2 * bu.x, F2I = s2 * bu.y;
        float n1R = z1R + mB * z2R + F1R;
        z2R = mC * z1R + mD * z2R + F2R;
        z1R = n1R;
        float n1I = z1I + mB * z2I + F1I;
        z2I = mC * z1I + mD * z2I + F2I;
        z1I = n1I;
    }
    g_T[bc * 256 + p] = make_float4(z1R, z2R, z1I, z2I);
}

// ---------------------------------------------------------------------------
// Pass 2: sequential combine over chunks. Mp = M^LCH via 7 squarings.
// Writes prefix state entering each chunk. Thread = p, block = b.
// ---------------------------------------------------------------------------
__global__ void scan_combine(const float* __restrict__ sp, const float* __restrict__ ap)
{
    int p = threadIdx.x, b = blockIdx.x;
    float s, s2, mB, mC, mD;
    get_params(sp, ap, p, s, s2, mB, mC, mD);

    float a11 = 1.f, a12 = mB, a21 = mC, a22 = mD;
#pragma unroll
    for (int i = 0; i < LOG_LCH; i++) {
        float n11 = a11 * a11 + a12 * a21;
        float n12 = a12 * (a11 + a22);
        float n21 = a21 * (a11 + a22);
        float n22 = a12 * a21 + a22 * a22;
        a11 = n11; a12 = n12; a21 = n21; a22 = n22;
    }

    float z1R = 0.f, z2R = 0.f, z1I = 0.f, z2I = 0.f;
    for (int c = 0; c < NC; c++) {
        int idx = (b * NC + c) * 256 + p;
        g_S[idx] = make_float4(z1R, z2R, z1I, z2I);
        float4 t = g_T[idx];
        float n1R = a11 * z1R + a12 * z2R + t.x;
        float n2R = a21 * z1R + a22 * z2R + t.y;
        z1R = n1R; z2R = n2R;
        float n1I = a11 * z1I + a12 * z2I + t.z;
        float n2I = a21 * z1I + a22 * z2I + t.w;
        z1I = n1I; z2I = n2I;
    }
}

// ---------------------------------------------------------------------------
// Pass 3: re-scan each chunk from its true prefix, write ys = z2 (R,I).
// ---------------------------------------------------------------------------
__global__ void scan_final(const float* __restrict__ sp, const float* __restrict__ ap)
{
    int p = threadIdx.x;
    int bc = blockIdx.x;
    int b = bc / NC, c = bc % NC;
    float s, s2, mB, mC, mD;
    get_params(sp, ap, p, s, s2, mB, mC, mD);

    float4 s0 = g_S[bc * 256 + p];
    float z1R = s0.x, z2R = s0.y, z1I = s0.z, z2I = s0.w;

    size_t base = (size_t)(b * L_ + c * LCH) * 512;
    const float2* Bp = (const float2*)(g_Bu + base) + p;
    float2* Yp = (float2*)(g_ys + base) + p;

#pragma unroll 4
    for (int j = 0; j < LCH; j++) {
        float2 bu = Bp[(size_t)j * 256];
        float F1R = s * bu.x,  F1I = s * bu.y;
        float F2R = s2 * bu.x, F2I = s2 * bu.y;
        float n1R = z1R + mB * z2R + F1R;
        z2R = mC * z1R + mD * z2R + F2R;
        z1R = n1R;
        float n1I = z1I + mB * z2I + F1I;
        z2I = mC * z1I + mD * z2I + F2I;
        z1I = n1I;
        Yp[(size_t)j * 256] = make_float2(z2R, z2I);
    }
}

// ---------------------------------------------------------------------------
// fp32 SIMT GEMM: C[m][n] = sum_k A[m][k] * W[n][k]
// 128x128 block tile, BK=8, 256 threads, 8x8 microtile, double-buffered smem.
// MODE 0: A = x (param),  W = g_Wg, C = g_Bu
// MODE 1: A = g_ys,       W = g_W2, C = y (param), epilogue += D[n]*x[m][n]
// ---------------------------------------------------------------------------
template <int MODE>
__global__ void __launch_bounds__(256)
sgemm_kernel(const float* __restrict__ Xin, float* __restrict__ Yout,
             const float* __restrict__ Dvec)
{
    const float* A = (MODE == 0) ? Xin : g_ys;
    const float* W = (MODE == 0) ? g_Wg : g_W2;
    float* Cout    = (MODE == 0) ? g_Bu : Yout;

    __shared__ float As[2][8][128];
    __shared__ float Ws[2][8][128];

    int tid = threadIdx.x;
    int bm = blockIdx.y * 128;
    int bn = blockIdx.x * 128;

    int lr = tid >> 1;            // 0..127: tile row for loading
    int lc = (tid & 1) << 2;      // 0 or 4: k offset (float4)

    const float* Ag  = A + (size_t)(bm + lr) * 512 + lc;
    const float* Wgp = W + (size_t)(bn + lr) * 512 + lc;

    float acc[8][8];
#pragma unroll
    for (int i = 0; i < 8; i++)
#pragma unroll
        for (int j = 0; j < 8; j++) acc[i][j] = 0.f;

    int tx = tid & 15, ty = tid >> 4;
    int row0 = ty * 4, row1 = 64 + ty * 4;
    int col0 = tx * 4, col1 = 64 + tx * 4;

    // prologue: tile 0
    {
        float4 av = *(const float4*)Ag;
        float4 wv = *(const float4*)Wgp;
        As[0][lc + 0][lr] = av.x; As[0][lc + 1][lr] = av.y;
        As[0][lc + 2][lr] = av.z; As[0][lc + 3][lr] = av.w;
        Ws[0][lc + 0][lr] = wv.x; Ws[0][lc + 1][lr] = wv.y;
        Ws[0][lc + 2][lr] = wv.z; Ws[0][lc + 3][lr] = wv.w;
    }
    __syncthreads();

    int buf = 0;
    for (int kt = 0; kt < 64; kt++) {
        float4 av2, wv2;
        if (kt < 63) {
            av2 = *(const float4*)(Ag + (kt + 1) * 8);
            wv2 = *(const float4*)(Wgp + (kt + 1) * 8);
        }
#pragma unroll
        for (int k = 0; k < 8; k++) {
            float ar[8], br[8];
            *(float4*)&ar[0] = *(const float4*)&As[buf][k][row0];
            *(float4*)&ar[4] = *(const float4*)&As[buf][k][row1];
            *(float4*)&br[0] = *(const float4*)&Ws[buf][k][col0];
            *(float4*)&br[4] = *(const float4*)&Ws[buf][k][col1];
#pragma unroll
            for (int i = 0; i < 8; i++)
#pragma unroll
                for (int j = 0; j < 8; j++)
                    acc[i][j] = fmaf(ar[i], br[j], acc[i][j]);
        }
        if (kt < 63) {
            int nb = buf ^ 1;
            As[nb][lc + 0][lr] = av2.x; As[nb][lc + 1][lr] = av2.y;
            As[nb][lc + 2][lr] = av2.z; As[nb][lc + 3][lr] = av2.w;
            Ws[nb][lc + 0][lr] = wv2.x; Ws[nb][lc + 1][lr] = wv2.y;
            Ws[nb][lc + 2][lr] = wv2.z; Ws[nb][lc + 3][lr] = wv2.w;
        }
        __syncthreads();
        buf ^= 1;
    }

    // epilogue
    float4 d0, d1;
    if (MODE == 1) {
        d0 = *(const float4*)(Dvec + bn + col0);
        d1 = *(const float4*)(Dvec + bn + col1);
    }
#pragma unroll
    for (int i = 0; i < 8; i++) {
        int r = (i < 4) ? (row0 + i) : (row1 + i - 4);
        size_t off = (size_t)(bm + r) * 512 + bn;
        float4 v0 = make_float4(acc[i][0], acc[i][1], acc[i][2], acc[i][3]);
        float4 v1 = make_float4(acc[i][4], acc[i][5], acc[i][6], acc[i][7]);
        if (MODE == 1) {
            float4 x0 = *(const float4*)(Xin + off + col0);
            float4 x1 = *(const float4*)(Xin + off + col1);
            v0.x += d0.x * x0.x; v0.y += d0.y * x0.y;
            v0.z += d0.z * x0.z; v0.w += d0.w * x0.w;
            v1.x += d1.x * x1.x; v1.y += d1.y * x1.y;
            v1.z += d1.z * x1.z; v1.w += d1.w * x1.w;
        }
        *(float4*)(Cout + off + col0) = v0;
        *(float4*)(Cout + off + col1) = v1;
    }
}

// ---------------------------------------------------------------------------
// Launch: prep -> GEMM1 -> scan(3 passes) -> GEMM2(+D*x)
// All on default stream; graph-capturable; no allocations.
// ---------------------------------------------------------------------------
extern "C" void kernel_launch(void* const* d_in, const int* in_sizes, int n_in,
                              void* d_out, int out_size)
{
    const float* x  = (const float*)d_in[0];
    const float* sp = (const float*)d_in[1];
    const float* ap = (const float*)d_in[2];
    const float* B  = (const float*)d_in[3];
    const float* C  = (const float*)d_in[4];
    const float* D  = (const float*)d_in[5];
    float* y = (float*)d_out;

    prep_weights<<<512, 256>>>(B, C);

    dim3 g1(4, 512);  // (N/128, M/128)
    sgemm_kernel<0><<<g1, 256>>>(x, nullptr, nullptr);

    scan_partial<<<BT_ * NC, 256>>>(sp, ap);
    scan_combine<<<BT_, 256>>>(sp, ap);
    scan_final<<<BT_ * NC, 256>>>(sp, ap);

    sgemm_kernel<1><<<g1, 256>>>(x, y, D);
}

// round 4
// speedup vs baseline: 2.2348x; 2.2348x over previous
#include <cuda_runtime.h>
#include <cuda_bf16.h>
#include <math.h>
#include <cstdint>

// Problem dims (fixed)
#define BT_  8
#define L_   8192
#define M_TOT 65536            // BT_*L_
#define NC   64                // chunks per sequence
#define LCH  128               // L_/NC
#define LOG_LCH 7

// ---------------------------------------------------------------------------
// Scratch (device globals — allocation-free per harness rules)
// ---------------------------------------------------------------------------
__device__ float g_Bu[(size_t)M_TOT * 512];       // GEMM1 out [m][2p + (0=R,1=I)]
__device__ __nv_bfloat16 g_xh[(size_t)M_TOT * 512];  // x split hi
__device__ __nv_bfloat16 g_xl[(size_t)M_TOT * 512];  // x split lo
__device__ __nv_bfloat16 g_yh[(size_t)M_TOT * 512];  // ys split hi (scan_final out)
__device__ __nv_bfloat16 g_yl[(size_t)M_TOT * 512];  // ys split lo
__device__ __nv_bfloat16 g_W1h[512 * 512];        // GEMM1 weight [n=2p+c][h]
__device__ __nv_bfloat16 g_W1l[512 * 512];
__device__ __nv_bfloat16 g_W2h[512 * 512];        // GEMM2 weight [n=h][k=2p+c]
__device__ __nv_bfloat16 g_W2l[512 * 512];
__device__ float4 g_T[BT_ * NC * 256];            // chunk-local final states
__device__ float4 g_S[BT_ * NC * 256];            // chunk prefix states

// ---------------------------------------------------------------------------
// Helpers (all sm_80-level: cp.async / ldmatrix / mma.sync — legal on sm_100)
// ---------------------------------------------------------------------------
__device__ __forceinline__ uint32_t smem_u32(const void* p) {
    uint32_t a;
    asm("{ .reg .u64 t; cvta.to.shared.u64 t, %1; cvt.u32.u64 %0, t; }" : "=r"(a) : "l"(p));
    return a;
}
__device__ __forceinline__ uint32_t swz(uint32_t off) { return off ^ ((off >> 3) & 0x70); }

#define CP_ASYNC16(dst_u32, src_ptr) \
    asm volatile("cp.async.cg.shared.global [%0], [%1], 16;" \
                 :: "r"(dst_u32), "l"(src_ptr) : "memory")
#define CP_COMMIT() asm volatile("cp.async.commit_group;" ::: "memory")
#define CP_WAIT1()  asm volatile("cp.async.wait_group 1;" ::: "memory")

#define LDSM4(r, addr) \
    asm volatile("ldmatrix.sync.aligned.m8n8.x4.shared.b16 {%0,%1,%2,%3}, [%4];" \
                 : "=r"((r)[0]), "=r"((r)[1]), "=r"((r)[2]), "=r"((r)[3]) : "r"(addr))

__device__ __forceinline__ void mma16816(float* d, const uint32_t* a, uint32_t b0, uint32_t b1) {
    asm volatile("mma.sync.aligned.m16n8k16.row.col.f32.bf16.bf16.f32 "
                 "{%0,%1,%2,%3}, {%4,%5,%6,%7}, {%8,%9}, {%0,%1,%2,%3};"
                 : "+f"(d[0]), "+f"(d[1]), "+f"(d[2]), "+f"(d[3])
                 : "r"(a[0]), "r"(a[1]), "r"(a[2]), "r"(a[3]), "r"(b0), "r"(b1));
}

// bf16 hi/lo split packing
__device__ __forceinline__ uint32_t bf16_bits(float v) {
    return (uint32_t)__bfloat16_as_ushort(__float2bfloat16_rn(v));
}
__device__ __forceinline__ uint32_t pack_hi_lo(float a, float b, uint32_t& lo_out) {
    uint32_t ha = bf16_bits(a), hb = bf16_bits(b);
    float ra = __bfloat162float(__ushort_as_bfloat16((unsigned short)ha));
    float rb = __bfloat162float(__ushort_as_bfloat16((unsigned short)hb));
    uint32_t la = bf16_bits(a - ra), lb = bf16_bits(b - rb);
    lo_out = la | (lb << 16);
    return ha | (hb << 16);
}

// ---------------------------------------------------------------------------
// Prep: weights (complex pack + hi/lo split) and x (hi/lo split)
// ---------------------------------------------------------------------------
__device__ __forceinline__ void split_store(__nv_bfloat16* Wh, __nv_bfloat16* Wl,
                                            size_t idx, float v) {
    __nv_bfloat16 h = __float2bfloat16_rn(v);
    Wh[idx] = h;
    Wl[idx] = __float2bfloat16_rn(v - __bfloat162float(h));
}
__global__ void prep_weights(const float* __restrict__ B, const float* __restrict__ C)
{
    int i = blockIdx.x * blockDim.x + threadIdx.x;  // 0 .. 131071
    int p = i >> 9;
    int h = i & 511;
    float br = B[((p << 9) + h) * 2 + 0];
    float bi = B[((p << 9) + h) * 2 + 1];
    float cr = C[((h << 8) + p) * 2 + 0];
    float ci = -C[((h << 8) + p) * 2 + 1];
    split_store(g_W1h, g_W1l, (size_t)(2 * p) * 512 + h, br);
    split_store(g_W1h, g_W1l, (size_t)(2 * p + 1) * 512 + h, bi);
    split_store(g_W2h, g_W2l, (size_t)(h << 9) + 2 * p, cr);
    split_store(g_W2h, g_W2l, (size_t)(h << 9) + 2 * p + 1, ci);
}

__global__ void prep_x(const float* __restrict__ x)
{
    size_t i = (size_t)blockIdx.x * 256 + threadIdx.x;  // 0 .. 8388607 (float4 units)
    float4 v = ((const float4*)x)[i];
    uint32_t l0, l1;
    uint32_t h0 = pack_hi_lo(v.x, v.y, l0);
    uint32_t h1 = pack_hi_lo(v.z, v.w, l1);
    ((uint2*)g_xh)[i] = make_uint2(h0, h1);
    ((uint2*)g_xl)[i] = make_uint2(l0, l1);
}

// ---------------------------------------------------------------------------
// Transition parameters (reference fp32 rounding; sigmoid in double)
// ---------------------------------------------------------------------------
__device__ __forceinline__ void get_params(const float* __restrict__ sp,
                                           const float* __restrict__ ap, int p,
                                           float& s, float& s2,
                                           float& mB, float& mC, float& mD)
{
    double sd = 1.0 / (1.0 + exp(-(double)sp[p]));
    s = (float)sd;
    float a = fmaxf(ap[p], 0.0f);
    mB = -__fmul_rn(s, a);
    mC = s;
    s2 = __fmul_rn(s, s);
    mD = __fsub_rn(1.0f, __fmul_rn(s2, a));
}

// ---------------------------------------------------------------------------
// Pass 1: per-chunk local scan from zero
// ---------------------------------------------------------------------------
__global__ void scan_partial(const float* __restrict__ sp, const float* __restrict__ ap)
{
    int p = threadIdx.x;
    int bc = blockIdx.x;
    int b = bc / NC, c = bc % NC;
    float s, s2, mB, mC, mD;
    get_params(sp, ap, p, s, s2, mB, mC, mD);

    float z1R = 0.f, z2R = 0.f, z1I = 0.f, z2I = 0.f;
    const float2* Bp = (const float2*)(g_Bu + (size_t)(b * L_ + c * LCH) * 512) + p;

#pragma unroll 4
    for (int j = 0; j < LCH; j++) {
        float2 bu = Bp[(size_t)j * 256];
        float F1R = s * bu.x,  F1I = s * bu.y;
        float F2R = s2 * bu.x, F2I = s2 * bu.y;
        float n1R = z1R + mB * z2R + F1R;
        z2R = mC * z1R + mD * z2R + F2R;
        z1R = n1R;
        float n1I = z1I + mB * z2I + F1I;
        z2I = mC * z1I + mD * z2I + F2I;
        z1I = n1I;
    }
    g_T[bc * 256 + p] = make_float4(z1R, z2R, z1I, z2I);
}

// ---------------------------------------------------------------------------
// Pass 2: sequential combine over chunks (R/I split across blocks; MLP=8)
// ---------------------------------------------------------------------------
__global__ void scan_combine(const float* __restrict__ sp, const float* __restrict__ ap)
{
    int p = threadIdx.x;
    int b = blockIdx.x >> 1;
    int ri = blockIdx.x & 1;
    float s, s2, mB, mC, mD;
    get_params(sp, ap, p, s, s2, mB, mC, mD);

    float a11 = 1.f, a12 = mB, a21 = mC, a22 = mD;
#pragma unroll
    for (int i = 0; i < LOG_LCH; i++) {
        float n11 = a11 * a11 + a12 * a21;
        float n12 = a12 * (a11 + a22);
        float n21 = a21 * (a11 + a22);
        float n22 = a12 * a21 + a22 * a22;
        a11 = n11; a12 = n12; a21 = n21; a22 = n22;
    }

    const float2* T2 = (const float2*)g_T;
    float2* S2 = (float2*)g_S;
    float z1 = 0.f, z2 = 0.f;
    for (int c0 = 0; c0 < NC; c0 += 8) {
        float2 t[8];
#pragma unroll
        for (int q = 0; q < 8; q++)
            t[q] = T2[((size_t)((b * NC + c0 + q) * 256 + p)) * 2 + ri];
#pragma unroll
        for (int q = 0; q < 8; q++) {
            S2[((size_t)((b * NC + c0 + q) * 256 + p)) * 2 + ri] = make_float2(z1, z2);
            float n1 = a11 * z1 + a12 * z2 + t[q].x;
            z2 = a21 * z1 + a22 * z2 + t[q].y;
            z1 = n1;
        }
    }
}

// ---------------------------------------------------------------------------
// Pass 3: re-scan from true prefix; write ys directly as bf16 hi/lo pairs
// (col 2p = Re, col 2p+1 = Im), ready for GEMM2's K layout.
// ---------------------------------------------------------------------------
__global__ void scan_final(const float* __restrict__ sp, const float* __restrict__ ap)
{
    int p = threadIdx.x;
    int bc = blockIdx.x;
    int b = bc / NC, c = bc % NC;
    float s, s2, mB, mC, mD;
    get_params(sp, ap, p, s, s2, mB, mC, mD);

    float4 s0 = g_S[bc * 256 + p];
    float z1R = s0.x, z2R = s0.y, z1I = s0.z, z2I = s0.w;

    size_t base = (size_t)(b * L_ + c * LCH) * 512;
    const float2* Bp = (const float2*)(g_Bu + base) + p;
    uint32_t* Yh = (uint32_t*)(g_yh + base) + p;
    uint32_t* Yl = (uint32_t*)(g_yl + base) + p;

#pragma unroll 4
    for (int j = 0; j < LCH; j++) {
        float2 bu = Bp[(size_t)j * 256];
        float F1R = s * bu.x,  F1I = s * bu.y;
        float F2R = s2 * bu.x, F2I = s2 * bu.y;
        float n1R = z1R + mB * z2R + F1R;
        z2R = mC * z1R + mD * z2R + F2R;
        z1R = n1R;
        float n1I = z1I + mB * z2I + F1I;
        z2I = mC * z1I + mD * z2I + F2I;
        z1I = n1I;
        uint32_t lo;
        uint32_t hi = pack_hi_lo(z2R, z2I, lo);
        Yh[(size_t)j * 256] = hi;
        Yl[(size_t)j * 256] = lo;
    }
}

// ---------------------------------------------------------------------------
// bf16x3-split mma.sync GEMM: C[m][n] = sum_k A[m][k]*W[n][k]  (fp32-accurate)
//   BM=128, BN=128, BK=64, 2-stage cp.async pipeline, 8 warps @ 64x32,
//   3 pairings per k16: Ah*Wh + Ah*Wl + Al*Wh.
// MODE 0: A = g_xh/g_xl, W = g_W1h/l, C = g_Bu
// MODE 1: A = g_yh/g_yl, W = g_W2h/l, C = y, epilogue += D[n]*x[m][n]
//
// Stage layout (64KB): Ah +0, Al +16K, Wh +32K, Wl +48K; rows = 128B, SW128.
// ---------------------------------------------------------------------------
#define STAGE_BYTES 65536
#define OFF_AH 0
#define OFF_AL 16384
#define OFF_BH 32768
#define OFF_BL 49152
#define GEMM_SMEM (2 * STAGE_BYTES)

template <int MODE>
__global__ void __launch_bounds__(256, 1)
mma_gemm(const float* __restrict__ Xin, float* __restrict__ Yout,
         const float* __restrict__ Dvec)
{
    extern __shared__ char smem[];
    const uint32_t sb = smem_u32(smem);
    const int tid = threadIdx.x, wid = tid >> 5, lane = tid & 31;
    const int bm = blockIdx.y * 128, bn = blockIdx.x * 128;

    const __nv_bfloat16* Ah = (MODE == 0) ? g_xh : g_yh;
    const __nv_bfloat16* Al = (MODE == 0) ? g_xl : g_yl;
    const __nv_bfloat16* Wh = (MODE == 0) ? g_W1h : g_W2h;
    const __nv_bfloat16* Wl = (MODE == 0) ? g_W1l : g_W2l;
    float* Cout = (MODE == 0) ? g_Bu : Yout;

    // ---- stage loader: 64KB via 16 cp.async.16B per thread ----
    auto load_stage = [&](int kb, int s) {
        uint32_t base = sb + s * STAGE_BYTES;
#pragma unroll
        for (int i = 0; i < 4; i++) {
            int chunk = tid + i * 256;            // 0..1023
            int row = chunk >> 3, cc = chunk & 7; // row 0..127, 16B-chunk 0..7
            uint32_t so = swz((uint32_t)(row * 128 + cc * 16));
            size_t aoff = (size_t)(bm + row) * 512 + kb * 64 + cc * 8;
            size_t boff = (size_t)(bn + row) * 512 + kb * 64 + cc * 8;
            CP_ASYNC16(base + OFF_AH + so, Ah + aoff);
            CP_ASYNC16(base + OFF_AL + so, Al + aoff);
            CP_ASYNC16(base + OFF_BH + so, Wh + boff);
            CP_ASYNC16(base + OFF_BL + so, Wl + boff);
        }
    };

    // ---- per-warp/lane ldmatrix byte offsets (pre-swizzle) ----
    const int warp_m = (wid >> 2) * 64;   // 0 | 64
    const int warp_n = (wid & 3) * 32;    // 0,32,64,96
    // A x4: lanes 0-15 -> rows m0..m0+15 @ k0; lanes 16-31 -> same rows @ k0+8
    const uint32_t aByte = (uint32_t)((warp_m + (lane & 15)) * 128 + (lane >> 4) * 16);
    // B x4: lanes 0-7: n0..7@k0, 8-15: n0..7@k0+8, 16-23: n8..15@k0, 24-31: n8..15@k0+8
    const uint32_t bByte = (uint32_t)((warp_n + (lane & 7) + ((lane >> 4) << 3)) * 128
                                      + ((lane >> 3) & 1) * 16);

    float acc[4][4][4];
#pragma unroll
    for (int mf = 0; mf < 4; mf++)
#pragma unroll
        for (int nf = 0; nf < 4; nf++)
#pragma unroll
            for (int q = 0; q < 4; q++) acc[mf][nf][q] = 0.f;

    load_stage(0, 0); CP_COMMIT();
    load_stage(1, 1); CP_COMMIT();

    for (int kb = 0; kb < 8; kb++) {
        CP_WAIT1();              // groups complete in order -> stage kb ready
        __syncthreads();
        const uint32_t st = sb + (kb & 1) * STAGE_BYTES;
#pragma unroll
        for (int ks = 0; ks < 4; ks++) {
            const uint32_t ko = ks * 32;   // bytes along K (16 cols * 2B)
            uint32_t a[4][4], b[2][4], bl[2][4];
#pragma unroll
            for (int mf = 0; mf < 4; mf++)
                LDSM4(a[mf], st + OFF_AH + swz(aByte + mf * 2048 + ko));
#pragma unroll
            for (int bi = 0; bi < 2; bi++)
                LDSM4(b[bi], st + OFF_BH + swz(bByte + bi * 2048 + ko));
#pragma unroll
            for (int mf = 0; mf < 4; mf++)
#pragma unroll
                for (int nf = 0; nf < 4; nf++)
                    mma16816(acc[mf][nf], a[mf], b[nf >> 1][(nf & 1) * 2], b[nf >> 1][(nf & 1) * 2 + 1]);
#pragma unroll
            for (int bi = 0; bi < 2; bi++)
                LDSM4(bl[bi], st + OFF_BL + swz(bByte + bi * 2048 + ko));
#pragma unroll
            for (int mf = 0; mf < 4; mf++)
#pragma unroll
                for (int nf = 0; nf < 4; nf++)
                    mma16816(acc[mf][nf], a[mf], bl[nf >> 1][(nf & 1) * 2], bl[nf >> 1][(nf & 1) * 2 + 1]);
#pragma unroll
            for (int mf = 0; mf < 4; mf++)
                LDSM4(a[mf], st + OFF_AL + swz(aByte + mf * 2048 + ko));
#pragma unroll
            for (int mf = 0; mf < 4; mf++)
#pragma unroll
                for (int nf = 0; nf < 4; nf++)
                    mma16816(acc[mf][nf], a[mf], b[nf >> 1][(nf & 1) * 2], b[nf >> 1][(nf & 1) * 2 + 1]);
        }
        __syncthreads();        // all warps done reading this stage buffer
        if (kb + 2 < 8) load_stage(kb + 2, kb & 1);
        CP_COMMIT();            // uniform commit keeps group accounting simple
    }

    // ---- epilogue ----
    const int r = lane >> 2, cq = (lane & 3) * 2;
#pragma unroll
    for (int mf = 0; mf < 4; mf++) {
#pragma unroll
        for (int nf = 0; nf < 4; nf++) {
            int row0 = bm + warp_m + mf * 16 + r;
            int col = bn + warp_n + nf * 8 + cq;
            float2 v0 = make_float2(acc[mf][nf][0], acc[mf][nf][1]);
            float2 v1 = make_float2(acc[mf][nf][2], acc[mf][nf][3]);
            if (MODE == 1) {
                float2 dv = *(const float2*)(Dvec + col);
                float2 x0 = *(const float2*)(Xin + (size_t)row0 * 512 + col);
                float2 x1 = *(const float2*)(Xin + (size_t)(row0 + 8) * 512 + col);
                v0.x += dv.x * x0.x; v0.y += dv.y * x0.y;
                v1.x += dv.x * x1.x; v1.y += dv.y * x1.y;
            }
            *(float2*)(Cout + (size_t)row0 * 512 + col) = v0;
            *(float2*)(Cout + (size_t)(row0 + 8) * 512 + col) = v1;
        }
    }
}

// ---------------------------------------------------------------------------
// Launch: prep -> GEMM1 -> scan(3 passes) -> GEMM2(+D*x)
// ---------------------------------------------------------------------------
extern "C" void kernel_launch(void* const* d_in, const int* in_sizes, int n_in,
                              void* d_out, int out_size)
{
    const float* x  = (const float*)d_in[0];
    const float* sp = (const float*)d_in[1];
    const float* ap = (const float*)d_in[2];
    const float* B  = (const float*)d_in[3];
    const float* C  = (const float*)d_in[4];
    const float* D  = (const float*)d_in[5];
    float* y = (float*)d_out;

    cudaFuncSetAttribute(mma_gemm<0>, cudaFuncAttributeMaxDynamicSharedMemorySize, GEMM_SMEM);
    cudaFuncSetAttribute(mma_gemm<1>, cudaFuncAttributeMaxDynamicSharedMemorySize, GEMM_SMEM);

    prep_weights<<<512, 256>>>(B, C);
    prep_x<<<32768, 256>>>(x);

    dim3 g1(4, 512);  // (N/128 fast -> A tiles L2-reused, M/128)
    mma_gemm<0><<<g1, 256, GEMM_SMEM>>>(x, nullptr, nullptr);

    scan_partial<<<BT_ * NC, 256>>>(sp, ap);
    scan_combine<<<BT_ * 2, 256>>>(sp, ap);
    scan_final<<<BT_ * NC, 256>>>(sp, ap);

    mma_gemm<1><<<g1, 256, GEMM_SMEM>>>(x, y, D);
}